// round 11
// baseline (speedup 1.0000x reference)
#include <cuda_runtime.h>
#include <cuda_bf16.h>
#include <cstdint>

#define NTOK 8192
#define DIM  128
#define CIN  256
#define HWD  1024
#define LOG2E 1.4426950408889634f

// ---------------- device workspaces (no allocation allowed) ----------------
__device__ __align__(256) __nv_bfloat16 g_Q[NTOK * DIM];
__device__ __align__(256) __nv_bfloat16 g_K[NTOK * DIM];
__device__ __align__(256) __nv_bfloat16 g_V[NTOK * DIM];
__device__ __align__(256) float g_O[NTOK * DIM];
__device__ float g_logits[8 * HWD];
__device__ float g_sp[8 * HWD];

// ---------------- PTX helpers ----------------
__device__ __forceinline__ uint32_t smem_u32(const void* p) {
    return (uint32_t)__cvta_generic_to_shared(p);
}
__device__ __forceinline__ void ldsm_x4(uint32_t& r0, uint32_t& r1, uint32_t& r2, uint32_t& r3, uint32_t a) {
    asm volatile("ldmatrix.sync.aligned.m8n8.x4.shared.b16 {%0,%1,%2,%3},[%4];"
                 : "=r"(r0), "=r"(r1), "=r"(r2), "=r"(r3) : "r"(a));
}
__device__ __forceinline__ void ldsm_x4_t(uint32_t& r0, uint32_t& r1, uint32_t& r2, uint32_t& r3, uint32_t a) {
    asm volatile("ldmatrix.sync.aligned.m8n8.x4.trans.shared.b16 {%0,%1,%2,%3},[%4];"
                 : "=r"(r0), "=r"(r1), "=r"(r2), "=r"(r3) : "r"(a));
}
__device__ __forceinline__ void mma16816(float c[4], const uint32_t a[4], uint32_t b0, uint32_t b1) {
    asm volatile("mma.sync.aligned.m16n8k16.row.col.f32.bf16.bf16.f32 "
                 "{%0,%1,%2,%3},{%4,%5,%6,%7},{%8,%9},{%0,%1,%2,%3};"
                 : "+f"(c[0]), "+f"(c[1]), "+f"(c[2]), "+f"(c[3])
                 : "r"(a[0]), "r"(a[1]), "r"(a[2]), "r"(a[3]), "r"(b0), "r"(b1));
}
__device__ __forceinline__ float ex2f(float x) {
    float r; asm("ex2.approx.f32 %0,%1;" : "=f"(r) : "f"(x)); return r;
}
__device__ __forceinline__ uint32_t packbf(float lo, float hi) {
    uint32_t r; asm("cvt.rn.bf16x2.f32 %0,%1,%2;" : "=r"(r) : "f"(hi), "f"(lo)); return r;
}

// ==================== projections: x[8192,256] @ W[256,128] + b -> bf16 ====================
__global__ void proj_kernel(const float* __restrict__ x,
                            const float* __restrict__ Wt, const float* __restrict__ bt,
                            const float* __restrict__ Wp, const float* __restrict__ bp,
                            const float* __restrict__ Wa, const float* __restrict__ ba) {
    __shared__ float4 sx[32 * 64];   // [token][k4] : 32 tokens x 256 dims
    const int sel = blockIdx.y;
    const float* W    = (sel == 0) ? Wt : (sel == 1) ? Wp : Wa;
    const float* bias = (sel == 0) ? bt : (sel == 1) ? bp : ba;
    __nv_bfloat16* dst = (sel == 0) ? g_Q : (sel == 1) ? g_K : g_V;
    const int tid = threadIdx.x;
    const int t0 = blockIdx.x * 32;
    const float4* xg = (const float4*)(x + (size_t)t0 * CIN);
    for (int i = tid; i < 2048; i += 128) sx[i] = xg[i];
    __syncthreads();
    float acc[32];
#pragma unroll
    for (int t = 0; t < 32; ++t) acc[t] = 0.f;
    const int j = tid;
    for (int k4 = 0; k4 < 64; ++k4) {
        float w0 = W[(k4 * 4 + 0) * DIM + j];
        float w1 = W[(k4 * 4 + 1) * DIM + j];
        float w2 = W[(k4 * 4 + 2) * DIM + j];
        float w3 = W[(k4 * 4 + 3) * DIM + j];
#pragma unroll
        for (int t = 0; t < 32; ++t) {
            float4 v = sx[t * 64 + k4];
            acc[t] = fmaf(v.x, w0, acc[t]);
            acc[t] = fmaf(v.y, w1, acc[t]);
            acc[t] = fmaf(v.z, w2, acc[t]);
            acc[t] = fmaf(v.w, w3, acc[t]);
        }
    }
    float bj = bias[j];
#pragma unroll
    for (int t = 0; t < 32; ++t)
        dst[(size_t)(t0 + t) * DIM + j] = __float2bfloat16(acc[t] + bj);
}

// ==================== dense gate: logits[8,1024] += x_chunk @ Wd_chunk ====================
__global__ void zero_logits_kernel() {
    g_logits[blockIdx.x * 1024 + threadIdx.x] = 0.f;
}

__global__ void gate_partial(const float* __restrict__ x, const float* __restrict__ Wd) {
    __shared__ float xs[1024 * 8];   // [k_local][batch], 32KB
    const int tid = threadIdx.x;      // 256 threads; thread owns 4 cols j = tid*4..+3
    const int k0 = blockIdx.x * 1024;
    for (int i = tid; i < 8192; i += 256) {
        int b = i >> 10, kl = i & 1023;
        xs[kl * 8 + b] = x[(size_t)b * 262144 + k0 + kl];
    }
    __syncthreads();
    float4 acc[8];
#pragma unroll
    for (int b = 0; b < 8; ++b) acc[b] = make_float4(0.f, 0.f, 0.f, 0.f);
    const float4* Wv = (const float4*)Wd;   // 256 float4 per k-row
    for (int kl = 0; kl < 1024; ++kl) {
        float4 w = __ldcs(&Wv[(size_t)(k0 + kl) * 256 + tid]);
        float4 xa = *(const float4*)&xs[kl * 8];
        float4 xb = *(const float4*)&xs[kl * 8 + 4];
        float s;
        s = xa.x; acc[0].x = fmaf(w.x, s, acc[0].x); acc[0].y = fmaf(w.y, s, acc[0].y); acc[0].z = fmaf(w.z, s, acc[0].z); acc[0].w = fmaf(w.w, s, acc[0].w);
        s = xa.y; acc[1].x = fmaf(w.x, s, acc[1].x); acc[1].y = fmaf(w.y, s, acc[1].y); acc[1].z = fmaf(w.z, s, acc[1].z); acc[1].w = fmaf(w.w, s, acc[1].w);
        s = xa.z; acc[2].x = fmaf(w.x, s, acc[2].x); acc[2].y = fmaf(w.y, s, acc[2].y); acc[2].z = fmaf(w.z, s, acc[2].z); acc[2].w = fmaf(w.w, s, acc[2].w);
        s = xa.w; acc[3].x = fmaf(w.x, s, acc[3].x); acc[3].y = fmaf(w.y, s, acc[3].y); acc[3].z = fmaf(w.z, s, acc[3].z); acc[3].w = fmaf(w.w, s, acc[3].w);
        s = xb.x; acc[4].x = fmaf(w.x, s, acc[4].x); acc[4].y = fmaf(w.y, s, acc[4].y); acc[4].z = fmaf(w.z, s, acc[4].z); acc[4].w = fmaf(w.w, s, acc[4].w);
        s = xb.y; acc[5].x = fmaf(w.x, s, acc[5].x); acc[5].y = fmaf(w.y, s, acc[5].y); acc[5].z = fmaf(w.z, s, acc[5].z); acc[5].w = fmaf(w.w, s, acc[5].w);
        s = xb.z; acc[6].x = fmaf(w.x, s, acc[6].x); acc[6].y = fmaf(w.y, s, acc[6].y); acc[6].z = fmaf(w.z, s, acc[6].z); acc[6].w = fmaf(w.w, s, acc[6].w);
        s = xb.w; acc[7].x = fmaf(w.x, s, acc[7].x); acc[7].y = fmaf(w.y, s, acc[7].y); acc[7].z = fmaf(w.z, s, acc[7].z); acc[7].w = fmaf(w.w, s, acc[7].w);
    }
#pragma unroll
    for (int b = 0; b < 8; ++b) {
        float* p = &g_logits[b * HWD + tid * 4];
        atomicAdd(p + 0, acc[b].x);
        atomicAdd(p + 1, acc[b].y);
        atomicAdd(p + 2, acc[b].z);
        atomicAdd(p + 3, acc[b].w);
    }
}

__global__ void gate_softmax(const float* __restrict__ bd) {
    __shared__ float red[32];
    __shared__ float bc;
    const int b = blockIdx.x, j = threadIdx.x;
    const int lane = j & 31, w = j >> 5;
    float v = g_logits[b * HWD + j] + bd[j];
    float m = v;
#pragma unroll
    for (int o = 16; o; o >>= 1) m = fmaxf(m, __shfl_xor_sync(0xffffffffu, m, o));
    if (lane == 0) red[w] = m;
    __syncthreads();
    if (j < 32) {
        float t = red[j];
#pragma unroll
        for (int o = 16; o; o >>= 1) t = fmaxf(t, __shfl_xor_sync(0xffffffffu, t, o));
        if (j == 0) bc = t;
    }
    __syncthreads();
    float e = expf(v - bc);
    float s = e;
#pragma unroll
    for (int o = 16; o; o >>= 1) s += __shfl_xor_sync(0xffffffffu, s, o);
    if (lane == 0) red[w] = s;
    __syncthreads();
    if (j < 32) {
        float t = red[j];
#pragma unroll
        for (int o = 16; o; o >>= 1) t += __shfl_xor_sync(0xffffffffu, t, o);
        if (j == 0) bc = t;
    }
    __syncthreads();
    g_sp[b * HWD + j] = e / bc;
}

// ==================== flash attention over all 8192 tokens (bf16 mma) ====================
#define ROWP 136                 // padded bf16 row -> conflict-free ldmatrix
#define TILEB (64 * ROWP)        // elems per 64x128 tile
#define FLASH_SMEM (5 * TILEB * 2)

__device__ __forceinline__ void load_tile(__nv_bfloat16* dst, const __nv_bfloat16* src, int tid) {
#pragma unroll
    for (int it = 0; it < 8; ++it) {
        int c = tid + it * 128;
        int row = c >> 4, cc = c & 15;
        uint32_t d = smem_u32(dst + row * ROWP + cc * 8);
        const void* s = src + row * DIM + cc * 8;
        asm volatile("cp.async.cg.shared.global [%0],[%1],16;" :: "r"(d), "l"(s) : "memory");
    }
}

__global__ void __launch_bounds__(128, 1) flash_kernel() {
    extern __shared__ __align__(16) __nv_bfloat16 sh[];
    __nv_bfloat16* sQ = sh;
    __nv_bfloat16* sK = sh + TILEB;        // double buffered
    __nv_bfloat16* sV = sh + 3 * TILEB;    // double buffered
    const int tid = threadIdx.x, lane = tid & 31, warp = tid >> 5;
    const int q0 = blockIdx.x * 64;

    load_tile(sQ, g_Q + (size_t)q0 * DIM, tid);
    asm volatile("cp.async.commit_group;" ::: "memory");
    load_tile(sK, g_K, tid);
    load_tile(sV, g_V, tid);
    asm volatile("cp.async.commit_group;" ::: "memory");
    asm volatile("cp.async.wait_group 1;" ::: "memory");   // Q group done
    __syncthreads();

    // Q A-fragments: 8 k-tiles of 16
    uint32_t qf[8][4];
    {
        int row = warp * 16 + (lane & 7) + ((lane & 8) ? 8 : 0);
        int cb = (lane & 16) ? 8 : 0;
#pragma unroll
        for (int kk = 0; kk < 8; ++kk)
            ldsm_x4(qf[kk][0], qf[kk][1], qf[kk][2], qf[kk][3],
                    smem_u32(sQ + row * ROWP + kk * 16 + cb));
    }

    float oacc[16][4];
#pragma unroll
    for (int n = 0; n < 16; ++n) { oacc[n][0] = oacc[n][1] = oacc[n][2] = oacc[n][3] = 0.f; }
    float m0 = -1e30f, m1 = -1e30f, l0 = 0.f, l1 = 0.f;

    const int krow = (lane & 7) + ((lane & 16) ? 8 : 0);
    const int kc8  = (lane & 8) ? 8 : 0;
    const int vrow = (lane & 7) + ((lane & 8) ? 8 : 0);
    const int vc8  = (lane & 16) ? 8 : 0;

    for (int t = 0; t < 128; ++t) {
        const int buf = t & 1;
        if (t < 127) {
            load_tile(sK + (1 - buf) * TILEB, g_K + (size_t)(t + 1) * 64 * DIM, tid);
            load_tile(sV + (1 - buf) * TILEB, g_V + (size_t)(t + 1) * 64 * DIM, tid);
        }
        asm volatile("cp.async.commit_group;" ::: "memory");
        asm volatile("cp.async.wait_group 1;" ::: "memory");   // tile t ready
        __syncthreads();
        const __nv_bfloat16* kb = sK + buf * TILEB;
        const __nv_bfloat16* vb = sV + buf * TILEB;

        // S = Q K^T : 16 rows x 64 keys per warp
        float sacc[8][4];
#pragma unroll
        for (int n = 0; n < 8; ++n) { sacc[n][0] = sacc[n][1] = sacc[n][2] = sacc[n][3] = 0.f; }
#pragma unroll
        for (int kk = 0; kk < 8; ++kk) {
#pragma unroll
            for (int np = 0; np < 4; ++np) {
                uint32_t b0, b1, b2, b3;
                ldsm_x4(b0, b1, b2, b3, smem_u32(kb + (np * 16 + krow) * ROWP + kk * 16 + kc8));
                mma16816(sacc[2 * np],     qf[kk], b0, b1);
                mma16816(sacc[2 * np + 1], qf[kk], b2, b3);
            }
        }

        // online softmax: thread owns rows lane/4 and lane/4+8; quad reduce over lane^1, lane^2
        float mx0 = -1e30f, mx1 = -1e30f;
#pragma unroll
        for (int n = 0; n < 8; ++n) {
            mx0 = fmaxf(mx0, fmaxf(sacc[n][0], sacc[n][1]));
            mx1 = fmaxf(mx1, fmaxf(sacc[n][2], sacc[n][3]));
        }
        mx0 = fmaxf(mx0, __shfl_xor_sync(0xffffffffu, mx0, 1));
        mx0 = fmaxf(mx0, __shfl_xor_sync(0xffffffffu, mx0, 2));
        mx1 = fmaxf(mx1, __shfl_xor_sync(0xffffffffu, mx1, 1));
        mx1 = fmaxf(mx1, __shfl_xor_sync(0xffffffffu, mx1, 2));
        float mn0 = fmaxf(m0, mx0), mn1 = fmaxf(m1, mx1);
        float sc0 = ex2f((m0 - mn0) * LOG2E), sc1 = ex2f((m1 - mn1) * LOG2E);
        float rs0 = 0.f, rs1 = 0.f;
#pragma unroll
        for (int n = 0; n < 8; ++n) {
            sacc[n][0] = ex2f((sacc[n][0] - mn0) * LOG2E);
            sacc[n][1] = ex2f((sacc[n][1] - mn0) * LOG2E);
            sacc[n][2] = ex2f((sacc[n][2] - mn1) * LOG2E);
            sacc[n][3] = ex2f((sacc[n][3] - mn1) * LOG2E);
            rs0 += sacc[n][0] + sacc[n][1];
            rs1 += sacc[n][2] + sacc[n][3];
        }
        rs0 += __shfl_xor_sync(0xffffffffu, rs0, 1);
        rs0 += __shfl_xor_sync(0xffffffffu, rs0, 2);
        rs1 += __shfl_xor_sync(0xffffffffu, rs1, 1);
        rs1 += __shfl_xor_sync(0xffffffffu, rs1, 2);
        l0 = l0 * sc0 + rs0; l1 = l1 * sc1 + rs1;
        m0 = mn0; m1 = mn1;
#pragma unroll
        for (int n = 0; n < 16; ++n) {
            oacc[n][0] *= sc0; oacc[n][1] *= sc0;
            oacc[n][2] *= sc1; oacc[n][3] *= sc1;
        }

        // P: S accumulator frags -> bf16 A frags (pure register repack)
        uint32_t pf[4][4];
#pragma unroll
        for (int i = 0; i < 4; ++i) {
            pf[i][0] = packbf(sacc[2 * i][0],     sacc[2 * i][1]);
            pf[i][1] = packbf(sacc[2 * i][2],     sacc[2 * i][3]);
            pf[i][2] = packbf(sacc[2 * i + 1][0], sacc[2 * i + 1][1]);
            pf[i][3] = packbf(sacc[2 * i + 1][2], sacc[2 * i + 1][3]);
        }

        // O += P V : P[16x64] x V[64x128]
#pragma unroll
        for (int i = 0; i < 4; ++i) {
#pragma unroll
            for (int np = 0; np < 8; ++np) {
                uint32_t b0, b1, b2, b3;
                ldsm_x4_t(b0, b1, b2, b3, smem_u32(vb + (i * 16 + vrow) * ROWP + np * 16 + vc8));
                mma16816(oacc[2 * np],     pf[i], b0, b1);
                mma16816(oacc[2 * np + 1], pf[i], b2, b3);
            }
        }
        __syncthreads();   // all reads of buf done before next prefetch overwrites it
    }

    float inv0 = 1.f / l0, inv1 = 1.f / l1;
    int row0 = q0 + warp * 16 + (lane >> 2);
    int c0 = 2 * (lane & 3);
#pragma unroll
    for (int n = 0; n < 16; ++n) {
        int c = n * 8 + c0;
        *(float2*)&g_O[(size_t)row0 * DIM + c]       = make_float2(oacc[n][0] * inv0, oacc[n][1] * inv0);
        *(float2*)&g_O[(size_t)(row0 + 8) * DIM + c] = make_float2(oacc[n][2] * inv1, oacc[n][3] * inv1);
    }
}

// ==================== epilogue: (O @ W_mask) * sp + x ====================
__global__ void epilogue_kernel(const float* __restrict__ x, const float* __restrict__ Wm,
                                float* __restrict__ out) {
    __shared__ float4 sO[32 * 32];   // [token][k4], 32 tokens x 128 dims fp32
    __shared__ float ssp[32];
    const int tid = threadIdx.x;     // 256 threads; j = tid
    const int t0 = blockIdx.x * 32;
    const float4* og = (const float4*)(g_O + (size_t)t0 * DIM);
    for (int i = tid; i < 1024; i += 256) sO[i] = og[i];
    if (tid < 32) ssp[tid] = g_sp[t0 + tid];
    __syncthreads();
    const int j = tid;
    float acc[32];
#pragma unroll
    for (int t = 0; t < 32; ++t) acc[t] = 0.f;
    for (int k4 = 0; k4 < 32; ++k4) {
        float w0 = Wm[(k4 * 4 + 0) * CIN + j];
        float w1 = Wm[(k4 * 4 + 1) * CIN + j];
        float w2 = Wm[(k4 * 4 + 2) * CIN + j];
        float w3 = Wm[(k4 * 4 + 3) * CIN + j];
#pragma unroll
        for (int t = 0; t < 32; ++t) {
            float4 v = sO[t * 32 + k4];
            acc[t] = fmaf(v.x, w0, acc[t]);
            acc[t] = fmaf(v.y, w1, acc[t]);
            acc[t] = fmaf(v.z, w2, acc[t]);
            acc[t] = fmaf(v.w, w3, acc[t]);
        }
    }
#pragma unroll
    for (int t = 0; t < 32; ++t)
        out[(size_t)(t0 + t) * CIN + j] = acc[t] * ssp[t] + x[(size_t)(t0 + t) * CIN + j];
}

// ==================== launcher ====================
extern "C" void kernel_launch(void* const* d_in, const int* in_sizes, int n_in,
                              void* d_out, int out_size) {
    const float* x  = (const float*)d_in[0];
    const float* Wt = (const float*)d_in[1];
    const float* bt = (const float*)d_in[2];
    const float* Wp = (const float*)d_in[3];
    const float* bp = (const float*)d_in[4];
    const float* Wa = (const float*)d_in[5];
    const float* ba = (const float*)d_in[6];
    const float* Wm = (const float*)d_in[7];
    const float* Wd = (const float*)d_in[8];
    const float* bd = (const float*)d_in[9];
    float* out = (float*)d_out;

    // opt-in to >48KB dynamic smem (idempotent; also set on the uncaptured correctness call)
    cudaFuncSetAttribute(flash_kernel, cudaFuncAttributeMaxDynamicSharedMemorySize, FLASH_SMEM);

    zero_logits_kernel<<<8, 1024>>>();
    gate_partial<<<256, 256>>>(x, Wd);
    proj_kernel<<<dim3(256, 3), 128>>>(x, Wt, bt, Wp, bp, Wa, ba);
    flash_kernel<<<128, 128, FLASH_SMEM>>>();
    gate_softmax<<<8, 1024>>>(bd);
    epilogue_kernel<<<256, 256>>>(x, Wm, out);
}

// round 12
// speedup vs baseline: 1.1481x; 1.1481x over previous
#include <cuda_runtime.h>
#include <cuda_bf16.h>
#include <cstdint>

#define NTOK 8192
#define DIM  128
#define CIN  256
#define HWD  1024
#define LOG2E 1.4426950408889634f
#define NSPLIT 2          // KV splits for flash
#define KVTILES 64        // 64 key-tiles of 64 per split (128 total)

// ---------------- device workspaces (no allocation allowed) ----------------
__device__ __align__(256) __nv_bfloat16 g_Q[NTOK * DIM];
__device__ __align__(256) __nv_bfloat16 g_K[NTOK * DIM];
__device__ __align__(256) __nv_bfloat16 g_V[NTOK * DIM];
__device__ __align__(256) float g_Opart[NSPLIT * NTOK * DIM];  // unnormalized partials
__device__ float g_m[NSPLIT * NTOK];
__device__ float g_l[NSPLIT * NTOK];
__device__ float g_logits[8 * HWD];
__device__ float g_sp[8 * HWD];

// ---------------- PTX helpers ----------------
__device__ __forceinline__ uint32_t smem_u32(const void* p) {
    return (uint32_t)__cvta_generic_to_shared(p);
}
__device__ __forceinline__ void ldsm_x4(uint32_t& r0, uint32_t& r1, uint32_t& r2, uint32_t& r3, uint32_t a) {
    asm volatile("ldmatrix.sync.aligned.m8n8.x4.shared.b16 {%0,%1,%2,%3},[%4];"
                 : "=r"(r0), "=r"(r1), "=r"(r2), "=r"(r3) : "r"(a));
}
__device__ __forceinline__ void ldsm_x4_t(uint32_t& r0, uint32_t& r1, uint32_t& r2, uint32_t& r3, uint32_t a) {
    asm volatile("ldmatrix.sync.aligned.m8n8.x4.trans.shared.b16 {%0,%1,%2,%3},[%4];"
                 : "=r"(r0), "=r"(r1), "=r"(r2), "=r"(r3) : "r"(a));
}
__device__ __forceinline__ void mma16816(float c[4], const uint32_t a[4], uint32_t b0, uint32_t b1) {
    asm volatile("mma.sync.aligned.m16n8k16.row.col.f32.bf16.bf16.f32 "
                 "{%0,%1,%2,%3},{%4,%5,%6,%7},{%8,%9},{%0,%1,%2,%3};"
                 : "+f"(c[0]), "+f"(c[1]), "+f"(c[2]), "+f"(c[3])
                 : "r"(a[0]), "r"(a[1]), "r"(a[2]), "r"(a[3]), "r"(b0), "r"(b1));
}
__device__ __forceinline__ float ex2f(float x) {
    float r; asm("ex2.approx.f32 %0,%1;" : "=f"(r) : "f"(x)); return r;
}
__device__ __forceinline__ uint32_t packbf(float lo, float hi) {
    uint32_t r; asm("cvt.rn.bf16x2.f32 %0,%1,%2;" : "=r"(r) : "f"(hi), "f"(lo)); return r;
}

// ==================== projections: x[8192,256] @ W[256,128] + b -> bf16 ====================
__global__ void proj_kernel(const float* __restrict__ x,
                            const float* __restrict__ Wt, const float* __restrict__ bt,
                            const float* __restrict__ Wp, const float* __restrict__ bp,
                            const float* __restrict__ Wa, const float* __restrict__ ba) {
    __shared__ float4 sx[32 * 64];   // [token][k4] : 32 tokens x 256 dims
    const int sel = blockIdx.y;
    const float* W    = (sel == 0) ? Wt : (sel == 1) ? Wp : Wa;
    const float* bias = (sel == 0) ? bt : (sel == 1) ? bp : ba;
    __nv_bfloat16* dst = (sel == 0) ? g_Q : (sel == 1) ? g_K : g_V;
    const int tid = threadIdx.x;
    const int t0 = blockIdx.x * 32;
    const float4* xg = (const float4*)(x + (size_t)t0 * CIN);
    for (int i = tid; i < 2048; i += 128) sx[i] = xg[i];
    __syncthreads();
    float acc[32];
#pragma unroll
    for (int t = 0; t < 32; ++t) acc[t] = 0.f;
    const int j = tid;
    for (int k4 = 0; k4 < 64; ++k4) {
        float w0 = W[(k4 * 4 + 0) * DIM + j];
        float w1 = W[(k4 * 4 + 1) * DIM + j];
        float w2 = W[(k4 * 4 + 2) * DIM + j];
        float w3 = W[(k4 * 4 + 3) * DIM + j];
#pragma unroll
        for (int t = 0; t < 32; ++t) {
            float4 v = sx[t * 64 + k4];
            acc[t] = fmaf(v.x, w0, acc[t]);
            acc[t] = fmaf(v.y, w1, acc[t]);
            acc[t] = fmaf(v.z, w2, acc[t]);
            acc[t] = fmaf(v.w, w3, acc[t]);
        }
    }
    float bj = bias[j];
#pragma unroll
    for (int t = 0; t < 32; ++t)
        dst[(size_t)(t0 + t) * DIM + j] = __float2bfloat16(acc[t] + bj);
}

// ==================== dense gate: logits[8,1024] += x_chunk @ Wd_chunk ====================
__global__ void zero_logits_kernel() {
    g_logits[blockIdx.x * 1024 + threadIdx.x] = 0.f;
}

__global__ void gate_partial(const float* __restrict__ x, const float* __restrict__ Wd) {
    __shared__ float xs[1024 * 8];   // [k_local][batch], 32KB
    const int tid = threadIdx.x;      // 256 threads; thread owns 4 cols j = tid*4..+3
    const int k0 = blockIdx.x * 1024;
    for (int i = tid; i < 8192; i += 256) {
        int b = i >> 10, kl = i & 1023;
        xs[kl * 8 + b] = x[(size_t)b * 262144 + k0 + kl];
    }
    __syncthreads();
    float4 acc[8];
#pragma unroll
    for (int b = 0; b < 8; ++b) acc[b] = make_float4(0.f, 0.f, 0.f, 0.f);
    const float4* Wv = (const float4*)Wd;   // 256 float4 per k-row
#pragma unroll 2
    for (int kl = 0; kl < 1024; kl += 2) {
        float4 w0v = __ldcs(&Wv[(size_t)(k0 + kl) * 256 + tid]);
        float4 w1v = __ldcs(&Wv[(size_t)(k0 + kl + 1) * 256 + tid]);
        float4 xa0 = *(const float4*)&xs[kl * 8];
        float4 xb0 = *(const float4*)&xs[kl * 8 + 4];
        float4 xa1 = *(const float4*)&xs[kl * 8 + 8];
        float4 xb1 = *(const float4*)&xs[kl * 8 + 12];
        float s;
        s = xa0.x; acc[0].x = fmaf(w0v.x, s, acc[0].x); acc[0].y = fmaf(w0v.y, s, acc[0].y); acc[0].z = fmaf(w0v.z, s, acc[0].z); acc[0].w = fmaf(w0v.w, s, acc[0].w);
        s = xa0.y; acc[1].x = fmaf(w0v.x, s, acc[1].x); acc[1].y = fmaf(w0v.y, s, acc[1].y); acc[1].z = fmaf(w0v.z, s, acc[1].z); acc[1].w = fmaf(w0v.w, s, acc[1].w);
        s = xa0.z; acc[2].x = fmaf(w0v.x, s, acc[2].x); acc[2].y = fmaf(w0v.y, s, acc[2].y); acc[2].z = fmaf(w0v.z, s, acc[2].z); acc[2].w = fmaf(w0v.w, s, acc[2].w);
        s = xa0.w; acc[3].x = fmaf(w0v.x, s, acc[3].x); acc[3].y = fmaf(w0v.y, s, acc[3].y); acc[3].z = fmaf(w0v.z, s, acc[3].z); acc[3].w = fmaf(w0v.w, s, acc[3].w);
        s = xb0.x; acc[4].x = fmaf(w0v.x, s, acc[4].x); acc[4].y = fmaf(w0v.y, s, acc[4].y); acc[4].z = fmaf(w0v.z, s, acc[4].z); acc[4].w = fmaf(w0v.w, s, acc[4].w);
        s = xb0.y; acc[5].x = fmaf(w0v.x, s, acc[5].x); acc[5].y = fmaf(w0v.y, s, acc[5].y); acc[5].z = fmaf(w0v.z, s, acc[5].z); acc[5].w = fmaf(w0v.w, s, acc[5].w);
        s = xb0.z; acc[6].x = fmaf(w0v.x, s, acc[6].x); acc[6].y = fmaf(w0v.y, s, acc[6].y); acc[6].z = fmaf(w0v.z, s, acc[6].z); acc[6].w = fmaf(w0v.w, s, acc[6].w);
        s = xb0.w; acc[7].x = fmaf(w0v.x, s, acc[7].x); acc[7].y = fmaf(w0v.y, s, acc[7].y); acc[7].z = fmaf(w0v.z, s, acc[7].z); acc[7].w = fmaf(w0v.w, s, acc[7].w);
        s = xa1.x; acc[0].x = fmaf(w1v.x, s, acc[0].x); acc[0].y = fmaf(w1v.y, s, acc[0].y); acc[0].z = fmaf(w1v.z, s, acc[0].z); acc[0].w = fmaf(w1v.w, s, acc[0].w);
        s = xa1.y; acc[1].x = fmaf(w1v.x, s, acc[1].x); acc[1].y = fmaf(w1v.y, s, acc[1].y); acc[1].z = fmaf(w1v.z, s, acc[1].z); acc[1].w = fmaf(w1v.w, s, acc[1].w);
        s = xa1.z; acc[2].x = fmaf(w1v.x, s, acc[2].x); acc[2].y = fmaf(w1v.y, s, acc[2].y); acc[2].z = fmaf(w1v.z, s, acc[2].z); acc[2].w = fmaf(w1v.w, s, acc[2].w);
        s = xa1.w; acc[3].x = fmaf(w1v.x, s, acc[3].x); acc[3].y = fmaf(w1v.y, s, acc[3].y); acc[3].z = fmaf(w1v.z, s, acc[3].z); acc[3].w = fmaf(w1v.w, s, acc[3].w);
        s = xb1.x; acc[4].x = fmaf(w1v.x, s, acc[4].x); acc[4].y = fmaf(w1v.y, s, acc[4].y); acc[4].z = fmaf(w1v.z, s, acc[4].z); acc[4].w = fmaf(w1v.w, s, acc[4].w);
        s = xb1.y; acc[5].x = fmaf(w1v.x, s, acc[5].x); acc[5].y = fmaf(w1v.y, s, acc[5].y); acc[5].z = fmaf(w1v.z, s, acc[5].z); acc[5].w = fmaf(w1v.w, s, acc[5].w);
        s = xb1.z; acc[6].x = fmaf(w1v.x, s, acc[6].x); acc[6].y = fmaf(w1v.y, s, acc[6].y); acc[6].z = fmaf(w1v.z, s, acc[6].z); acc[6].w = fmaf(w1v.w, s, acc[6].w);
        s = xb1.w; acc[7].x = fmaf(w1v.x, s, acc[7].x); acc[7].y = fmaf(w1v.y, s, acc[7].y); acc[7].z = fmaf(w1v.z, s, acc[7].z); acc[7].w = fmaf(w1v.w, s, acc[7].w);
    }
#pragma unroll
    for (int b = 0; b < 8; ++b) {
        float* p = &g_logits[b * HWD + tid * 4];
        atomicAdd(p + 0, acc[b].x);
        atomicAdd(p + 1, acc[b].y);
        atomicAdd(p + 2, acc[b].z);
        atomicAdd(p + 3, acc[b].w);
    }
}

__global__ void gate_softmax(const float* __restrict__ bd) {
    __shared__ float red[32];
    __shared__ float bc;
    const int b = blockIdx.x, j = threadIdx.x;
    const int lane = j & 31, w = j >> 5;
    float v = g_logits[b * HWD + j] + bd[j];
    float m = v;
#pragma unroll
    for (int o = 16; o; o >>= 1) m = fmaxf(m, __shfl_xor_sync(0xffffffffu, m, o));
    if (lane == 0) red[w] = m;
    __syncthreads();
    if (j < 32) {
        float t = red[j];
#pragma unroll
        for (int o = 16; o; o >>= 1) t = fmaxf(t, __shfl_xor_sync(0xffffffffu, t, o));
        if (j == 0) bc = t;
    }
    __syncthreads();
    float e = expf(v - bc);
    float s = e;
#pragma unroll
    for (int o = 16; o; o >>= 1) s += __shfl_xor_sync(0xffffffffu, s, o);
    if (lane == 0) red[w] = s;
    __syncthreads();
    if (j < 32) {
        float t = red[j];
#pragma unroll
        for (int o = 16; o; o >>= 1) t += __shfl_xor_sync(0xffffffffu, t, o);
        if (j == 0) bc = t;
    }
    __syncthreads();
    g_sp[b * HWD + j] = e / bc;
}

// ==================== flash attention, split-KV x2 (bf16 mma) ====================
#define ROWP 136                 // padded bf16 row -> conflict-free ldmatrix
#define TILEB (64 * ROWP)        // elems per 64x128 tile
#define FLASH_SMEM (5 * TILEB * 2)

__device__ __forceinline__ void load_tile(__nv_bfloat16* dst, const __nv_bfloat16* src, int tid) {
#pragma unroll
    for (int it = 0; it < 8; ++it) {
        int c = tid + it * 128;
        int row = c >> 4, cc = c & 15;
        uint32_t d = smem_u32(dst + row * ROWP + cc * 8);
        const void* s = src + row * DIM + cc * 8;
        asm volatile("cp.async.cg.shared.global [%0],[%1],16;" :: "r"(d), "l"(s) : "memory");
    }
}

__global__ void __launch_bounds__(128, 2) flash_kernel() {
    extern __shared__ __align__(16) __nv_bfloat16 sh[];
    __nv_bfloat16* sQ = sh;
    __nv_bfloat16* sK = sh + TILEB;        // double buffered
    __nv_bfloat16* sV = sh + 3 * TILEB;    // double buffered
    const int tid = threadIdx.x, lane = tid & 31, warp = tid >> 5;
    const int q0 = blockIdx.x * 64;
    const int split = blockIdx.y;
    const __nv_bfloat16* Kbase = g_K + (size_t)split * KVTILES * 64 * DIM;
    const __nv_bfloat16* Vbase = g_V + (size_t)split * KVTILES * 64 * DIM;

    load_tile(sQ, g_Q + (size_t)q0 * DIM, tid);
    asm volatile("cp.async.commit_group;" ::: "memory");
    load_tile(sK, Kbase, tid);
    load_tile(sV, Vbase, tid);
    asm volatile("cp.async.commit_group;" ::: "memory");
    asm volatile("cp.async.wait_group 1;" ::: "memory");   // Q group done
    __syncthreads();

    // Q A-fragments: 8 k-tiles of 16
    uint32_t qf[8][4];
    {
        int row = warp * 16 + (lane & 7) + ((lane & 8) ? 8 : 0);
        int cb = (lane & 16) ? 8 : 0;
#pragma unroll
        for (int kk = 0; kk < 8; ++kk)
            ldsm_x4(qf[kk][0], qf[kk][1], qf[kk][2], qf[kk][3],
                    smem_u32(sQ + row * ROWP + kk * 16 + cb));
    }

    float oacc[16][4];
#pragma unroll
    for (int n = 0; n < 16; ++n) { oacc[n][0] = oacc[n][1] = oacc[n][2] = oacc[n][3] = 0.f; }
    float m0 = -1e30f, m1 = -1e30f, l0 = 0.f, l1 = 0.f;

    const int krow = (lane & 7) + ((lane & 16) ? 8 : 0);
    const int kc8  = (lane & 8) ? 8 : 0;
    const int vrow = (lane & 7) + ((lane & 8) ? 8 : 0);
    const int vc8  = (lane & 16) ? 8 : 0;

    for (int t = 0; t < KVTILES; ++t) {
        const int buf = t & 1;
        if (t < KVTILES - 1) {
            load_tile(sK + (1 - buf) * TILEB, Kbase + (size_t)(t + 1) * 64 * DIM, tid);
            load_tile(sV + (1 - buf) * TILEB, Vbase + (size_t)(t + 1) * 64 * DIM, tid);
        }
        asm volatile("cp.async.commit_group;" ::: "memory");
        asm volatile("cp.async.wait_group 1;" ::: "memory");   // tile t ready
        __syncthreads();
        const __nv_bfloat16* kb = sK + buf * TILEB;
        const __nv_bfloat16* vb = sV + buf * TILEB;

        // S = Q K^T : 16 rows x 64 keys per warp
        float sacc[8][4];
#pragma unroll
        for (int n = 0; n < 8; ++n) { sacc[n][0] = sacc[n][1] = sacc[n][2] = sacc[n][3] = 0.f; }
#pragma unroll
        for (int kk = 0; kk < 8; ++kk) {
#pragma unroll
            for (int np = 0; np < 4; ++np) {
                uint32_t b0, b1, b2, b3;
                ldsm_x4(b0, b1, b2, b3, smem_u32(kb + (np * 16 + krow) * ROWP + kk * 16 + kc8));
                mma16816(sacc[2 * np],     qf[kk], b0, b1);
                mma16816(sacc[2 * np + 1], qf[kk], b2, b3);
            }
        }

        // online softmax: thread owns rows (lane>>2) and +8; quad reduce
        float mx0 = -1e30f, mx1 = -1e30f;
#pragma unroll
        for (int n = 0; n < 8; ++n) {
            mx0 = fmaxf(mx0, fmaxf(sacc[n][0], sacc[n][1]));
            mx1 = fmaxf(mx1, fmaxf(sacc[n][2], sacc[n][3]));
        }
        mx0 = fmaxf(mx0, __shfl_xor_sync(0xffffffffu, mx0, 1));
        mx0 = fmaxf(mx0, __shfl_xor_sync(0xffffffffu, mx0, 2));
        mx1 = fmaxf(mx1, __shfl_xor_sync(0xffffffffu, mx1, 1));
        mx1 = fmaxf(mx1, __shfl_xor_sync(0xffffffffu, mx1, 2));
        float mn0 = fmaxf(m0, mx0), mn1 = fmaxf(m1, mx1);
        float sc0 = ex2f((m0 - mn0) * LOG2E), sc1 = ex2f((m1 - mn1) * LOG2E);
        float rs0 = 0.f, rs1 = 0.f;
#pragma unroll
        for (int n = 0; n < 8; ++n) {
            sacc[n][0] = ex2f((sacc[n][0] - mn0) * LOG2E);
            sacc[n][1] = ex2f((sacc[n][1] - mn0) * LOG2E);
            sacc[n][2] = ex2f((sacc[n][2] - mn1) * LOG2E);
            sacc[n][3] = ex2f((sacc[n][3] - mn1) * LOG2E);
            rs0 += sacc[n][0] + sacc[n][1];
            rs1 += sacc[n][2] + sacc[n][3];
        }
        rs0 += __shfl_xor_sync(0xffffffffu, rs0, 1);
        rs0 += __shfl_xor_sync(0xffffffffu, rs0, 2);
        rs1 += __shfl_xor_sync(0xffffffffu, rs1, 1);
        rs1 += __shfl_xor_sync(0xffffffffu, rs1, 2);
        l0 = l0 * sc0 + rs0; l1 = l1 * sc1 + rs1;
        m0 = mn0; m1 = mn1;
#pragma unroll
        for (int n = 0; n < 16; ++n) {
            oacc[n][0] *= sc0; oacc[n][1] *= sc0;
            oacc[n][2] *= sc1; oacc[n][3] *= sc1;
        }

        // P frags: accumulator -> bf16 A operand (register repack)
        uint32_t pf[4][4];
#pragma unroll
        for (int i = 0; i < 4; ++i) {
            pf[i][0] = packbf(sacc[2 * i][0],     sacc[2 * i][1]);
            pf[i][1] = packbf(sacc[2 * i][2],     sacc[2 * i][3]);
            pf[i][2] = packbf(sacc[2 * i + 1][0], sacc[2 * i + 1][1]);
            pf[i][3] = packbf(sacc[2 * i + 1][2], sacc[2 * i + 1][3]);
        }

        // O += P V
#pragma unroll
        for (int i = 0; i < 4; ++i) {
#pragma unroll
            for (int np = 0; np < 8; ++np) {
                uint32_t b0, b1, b2, b3;
                ldsm_x4_t(b0, b1, b2, b3, smem_u32(vb + (i * 16 + vrow) * ROWP + np * 16 + vc8));
                mma16816(oacc[2 * np],     pf[i], b0, b1);
                mma16816(oacc[2 * np + 1], pf[i], b2, b3);
            }
        }
        __syncthreads();   // buf fully consumed before next prefetch overwrites
    }

    // store UNNORMALIZED partial + (m,l)
    float* Op = g_Opart + (size_t)split * NTOK * DIM;
    int row0 = q0 + warp * 16 + (lane >> 2);
    int c0 = 2 * (lane & 3);
#pragma unroll
    for (int n = 0; n < 16; ++n) {
        int c = n * 8 + c0;
        *(float2*)&Op[(size_t)row0 * DIM + c]       = make_float2(oacc[n][0], oacc[n][1]);
        *(float2*)&Op[(size_t)(row0 + 8) * DIM + c] = make_float2(oacc[n][2], oacc[n][3]);
    }
    if ((lane & 3) == 0) {
        g_m[split * NTOK + row0] = m0;     g_l[split * NTOK + row0] = l0;
        g_m[split * NTOK + row0 + 8] = m1; g_l[split * NTOK + row0 + 8] = l1;
    }
}

// ==================== epilogue: combine splits, (O @ W_mask) * sp + x ====================
__global__ void epilogue_kernel(const float* __restrict__ x, const float* __restrict__ Wm,
                                float* __restrict__ out) {
    __shared__ float4 sO[32 * 32];   // [token][k4], combined O tile
    __shared__ float ssp[32], sw0[32], sw1[32], sinv[32];
    const int tid = threadIdx.x;     // 256 threads
    const int t0 = blockIdx.x * 32;
    if (tid < 32) {
        int r = t0 + tid;
        float m0 = g_m[r], m1 = g_m[NTOK + r];
        float l0 = g_l[r], l1 = g_l[NTOK + r];
        float mm = fmaxf(m0, m1);
        float w0 = ex2f((m0 - mm) * LOG2E), w1 = ex2f((m1 - mm) * LOG2E);
        sw0[tid] = w0; sw1[tid] = w1;
        sinv[tid] = 1.f / (l0 * w0 + l1 * w1);
        ssp[tid] = g_sp[r];
    }
    __syncthreads();
    const float4* o0 = (const float4*)(g_Opart + (size_t)t0 * DIM);
    const float4* o1 = (const float4*)(g_Opart + (size_t)NTOK * DIM + (size_t)t0 * DIM);
    for (int i = tid; i < 1024; i += 256) {
        int t = i >> 5;
        float w0 = sw0[t] * sinv[t], w1 = sw1[t] * sinv[t];
        float4 a = o0[i], b = o1[i];
        sO[i] = make_float4(a.x * w0 + b.x * w1, a.y * w0 + b.y * w1,
                            a.z * w0 + b.z * w1, a.w * w0 + b.w * w1);
    }
    __syncthreads();
    const int j = tid;
    float acc[32];
#pragma unroll
    for (int t = 0; t < 32; ++t) acc[t] = 0.f;
    for (int k4 = 0; k4 < 32; ++k4) {
        float w0 = Wm[(k4 * 4 + 0) * CIN + j];
        float w1 = Wm[(k4 * 4 + 1) * CIN + j];
        float w2 = Wm[(k4 * 4 + 2) * CIN + j];
        float w3 = Wm[(k4 * 4 + 3) * CIN + j];
#pragma unroll
        for (int t = 0; t < 32; ++t) {
            float4 v = sO[t * 32 + k4];
            acc[t] = fmaf(v.x, w0, acc[t]);
            acc[t] = fmaf(v.y, w1, acc[t]);
            acc[t] = fmaf(v.z, w2, acc[t]);
            acc[t] = fmaf(v.w, w3, acc[t]);
        }
    }
#pragma unroll
    for (int t = 0; t < 32; ++t)
        out[(size_t)(t0 + t) * CIN + j] = acc[t] * ssp[t] + x[(size_t)(t0 + t) * CIN + j];
}

// ==================== launcher ====================
extern "C" void kernel_launch(void* const* d_in, const int* in_sizes, int n_in,
                              void* d_out, int out_size) {
    const float* x  = (const float*)d_in[0];
    const float* Wt = (const float*)d_in[1];
    const float* bt = (const float*)d_in[2];
    const float* Wp = (const float*)d_in[3];
    const float* bp = (const float*)d_in[4];
    const float* Wa = (const float*)d_in[5];
    const float* ba = (const float*)d_in[6];
    const float* Wm = (const float*)d_in[7];
    const float* Wd = (const float*)d_in[8];
    const float* bd = (const float*)d_in[9];
    float* out = (float*)d_out;

    cudaFuncSetAttribute(flash_kernel, cudaFuncAttributeMaxDynamicSharedMemorySize, FLASH_SMEM);

    zero_logits_kernel<<<8, 1024>>>();
    gate_partial<<<256, 256>>>(x, Wd);
    proj_kernel<<<dim3(256, 3), 128>>>(x, Wt, bt, Wp, bp, Wa, ba);
    flash_kernel<<<dim3(128, NSPLIT), 128, FLASH_SMEM>>>();
    gate_softmax<<<8, 1024>>>(bd);
    epilogue_kernel<<<256, 256>>>(x, Wm, out);
}